// round 7
// baseline (speedup 1.0000x reference)
#include <cuda_runtime.h>
#include <cstdint>

// ============================================================================
// ConvBnA int8: implicit-GEMM 3x3 conv via mma.sync m16n8k32 s8 (sm_100 safe)
//   out[b][co][oh][ow] = f32(clip(((conv + t[co]) >> (-n[co])), amin, amax))
// R7: merged prepass (pack_x + pack_w in one launch), conv A-load hoisted
// ahead of the epilogue so cp.async overlaps the store burst.
// ============================================================================

#define B_IMG    32
#define CIN      128
#define HW       56
#define PW       58
#define IMG_ROWS 3456          // 27*128; rows >= 3364 only feed discarded pixels
#define GRID     148
#define NTHR     512

#define SWZ(o) ((o) ^ (((o) >> 3) & 0x70))

__device__ __align__(128) signed char g_xpad[(size_t)B_IMG * IMG_ROWS * CIN]; // 13.5 MB
__device__ __align__(128) signed char g_wpack[9 * 256 * CIN];                 // 288 KB

// ------------------------------- PTX helpers -------------------------------
__device__ __forceinline__ uint32_t smem_u32(const void* p) {
    uint32_t a;
    asm("{ .reg .u64 t; cvta.to.shared.u64 t, %1; cvt.u32.u64 %0, t; }"
        : "=r"(a) : "l"(p));
    return a;
}
#define CP16(sm, gp) \
    asm volatile("cp.async.cg.shared.global [%0], [%1], 16;" :: "r"(sm), "l"(gp) : "memory")
#define CP_COMMIT() asm volatile("cp.async.commit_group;" ::: "memory")
#define CP_WAIT1()  asm volatile("cp.async.wait_group 1;" ::: "memory")

__device__ __forceinline__ void ldm_x4(uint32_t* r, uint32_t addr) {
    asm volatile("ldmatrix.sync.aligned.m8n8.x4.shared.b16 {%0,%1,%2,%3}, [%4];"
                 : "=r"(r[0]), "=r"(r[1]), "=r"(r[2]), "=r"(r[3]) : "r"(addr));
}
__device__ __forceinline__ void mma_s8(int* c, const uint32_t* a, uint32_t b0, uint32_t b1) {
    asm volatile(
        "mma.sync.aligned.m16n8k32.row.col.s32.s8.s8.s32 "
        "{%0,%1,%2,%3}, {%4,%5,%6,%7}, {%8,%9}, {%0,%1,%2,%3};"
        : "+r"(c[0]), "+r"(c[1]), "+r"(c[2]), "+r"(c[3])
        : "r"(a[0]), "r"(a[1]), "r"(a[2]), "r"(a[3]), "r"(b0), "r"(b1));
}

// ------------------------------- merged pre-pass ----------------------------
// grid (32, 59), 256 threads.
//   blockIdx.y <  58 : pack x row h'=blockIdx.y of image b=blockIdx.x (pad fused)
//   blockIdx.y == 58 : pack 1/32 of the weights (fully coalesced reads)
__global__ void pack_kernel(const int* __restrict__ x, const int* __restrict__ w) {
    __shared__ unsigned char stage[128 * 57];
    int b = blockIdx.x, hp = blockIdx.y;
    int tid = threadIdx.x;     // 256

    if (hp == 58) {
        // weights: 32768 (co,ci) pairs / 32 blocks = 1024 per block, 4 per thread
        #pragma unroll
        for (int i = 0; i < 4; i++) {
            int pair = b * 1024 + i * 256 + tid;       // pair = co*128 + ci
            const int* src = w + (size_t)pair * 9;
            #pragma unroll
            for (int tap = 0; tap < 9; tap++)
                g_wpack[tap * 32768 + pair] = (signed char)src[tap];
        }
        return;
    }

    signed char* dst = g_xpad + ((size_t)b * IMG_ROWS + (size_t)hp * PW) * 128;
    if (hp == 0 || hp == 57) {            // full zero row: 58*128 B = 464 uint4
        for (int i = tid; i < 464; i += 256)
            reinterpret_cast<uint4*>(dst)[i] = make_uint4(0, 0, 0, 0);
        return;
    }
    // zero w'=0 and w'=57 columns
    if (tid < 16) {
        int seg = tid & 7, side = tid >> 3;
        reinterpret_cast<uint4*>(dst + (size_t)side * 57 * 128)[seg] = make_uint4(0, 0, 0, 0);
    }
    int h = hp - 1;
    const int* xb = x + (size_t)b * 128 * 3136 + h * 56;
    for (int flat = tid; flat < 128 * 64; flat += 256) {
        int c = flat >> 6, wv = flat & 63;
        if (wv < 56) stage[c * 57 + wv] = (unsigned char)xb[c * 3136 + wv];
    }
    __syncthreads();
    for (int f = tid; f < 56 * 32; f += 256) {
        int wv = f >> 5, c4 = f & 31;
        uint32_t v = (uint32_t)stage[(c4 * 4 + 0) * 57 + wv]
                   | ((uint32_t)stage[(c4 * 4 + 1) * 57 + wv] << 8)
                   | ((uint32_t)stage[(c4 * 4 + 2) * 57 + wv] << 16)
                   | ((uint32_t)stage[(c4 * 4 + 3) * 57 + wv] << 24);
        *reinterpret_cast<uint32_t*>(dst + (size_t)(1 + wv) * 128 + c4 * 4) = v;
    }
}

// ------------------------------- conv kernel --------------------------------
static constexpr int A_REGION_ROWS  = 248;
static constexpr int A_REGION_BYTES = A_REGION_ROWS * 128;  // 31744
static constexpr int SMEM_W   = 0;                          // 147456
static constexpr int SMEM_A   = 147456;                     // 2 * 31744
static constexpr int SMEM_TS  = 210944;
static constexpr int SMEM_MM  = 211968;
static constexpr int SMEM_TOTAL = 212992;

__global__ void __launch_bounds__(NTHR, 1)
conv_kernel(const int* __restrict__ tvec, const int* __restrict__ nvec,
            const int* __restrict__ amin, const int* __restrict__ amax,
            float* __restrict__ out) {
    extern __shared__ __align__(1024) char smem[];
    const uint32_t sb = smem_u32(smem);
    const int tid = threadIdx.x;
    const int lane = tid & 31;
    const int wid = tid >> 5;          // 0..15
    const int warp_m = wid & 3;        // 4 warps over 128 pixels (32 each)
    const int warp_n = wid >> 2;       // 4 warps over 128 co (32 each)
    const int half = blockIdx.x & 1;
    const int mt0 = blockIdx.x >> 1;
    const int ntiles = (831 - mt0) / 74 + 1;

    if (tid < 128) {
        int co = half * 128 + tid;
        *reinterpret_cast<int2*>(smem + SMEM_TS + tid * 8) = make_int2(tvec[co], -nvec[co]);
        *reinterpret_cast<int2*>(smem + SMEM_MM + tid * 8) = make_int2(amin[co], amax[co]);
    }

    auto issue_load = [&](int k, int u) {
        int mtile = mt0 + 74 * k;
        int b = mtile / 26, mt = mtile - b * 26;
        const signed char* src = g_xpad + ((size_t)b * IMG_ROWS + (size_t)mt * 128) * 128;
        uint32_t abase = sb + SMEM_A + u * A_REGION_BYTES;
        #pragma unroll
        for (int i = 0; i < 4; i++) {
            int flat = i * NTHR + tid;                     // 1984 granules
            if (flat < A_REGION_BYTES / 16) {
                int off = flat << 4;
                CP16(abase + SWZ(off), src + off);
            }
        }
    };

    // resident weights + first A regions
    {
        #pragma unroll 6
        for (int i = 0; i < 18; i++) {
            int flat = i * NTHR + tid;                     // [0,9216)
            int tap = flat >> 10;
            int r = (flat >> 3) & 127, seg = flat & 7;
            const signed char* gp =
                g_wpack + ((size_t)(tap * 256 + half * 128 + r) << 7) + (seg << 4);
            CP16(sb + SMEM_W + (tap << 14) + SWZ((r << 7) | (seg << 4)), gp);
        }
        issue_load(0, 0);
        CP_COMMIT();
        if (ntiles > 1) issue_load(1, 1);
        CP_COMMIT();
    }

    for (int k = 0; k < ntiles; k++) {
        const int u = k & 1;
        const uint32_t sbA = sb + SMEM_A + u * A_REGION_BYTES;
        CP_WAIT1();
        __syncthreads();

        int acc[2][4][4];
        #pragma unroll
        for (int mt = 0; mt < 2; mt++)
            #pragma unroll
            for (int nt = 0; nt < 4; nt++)
                #pragma unroll
                for (int r = 0; r < 4; r++) acc[mt][nt][r] = 0;

        const int a_row_lane = warp_m * 32 + (lane & 15);
        const int a_kb_lane  = (lane >> 4) << 4;
        const int b_row_lane = warp_n * 32 + (lane & 7) + ((lane & 16) >> 1);
        const int b_kb_lane  = (lane & 8) << 1;

        #pragma unroll
        for (int tap = 0; tap < 9; tap++) {
            const int kh = tap / 3;
            const int taprow = kh * PW + (tap - kh * 3);
            const uint32_t sbW = sb + SMEM_W + (tap << 14);
            #pragma unroll
            for (int ks = 0; ks < 4; ks++) {
                uint32_t a[2][4];
                #pragma unroll
                for (int mt = 0; mt < 2; mt++) {
                    int row = a_row_lane + mt * 16 + taprow;
                    ldm_x4(a[mt], sbA + SWZ(row * 128 + ks * 32 + a_kb_lane));
                }
                uint32_t bf[2][4];
                #pragma unroll
                for (int np = 0; np < 2; np++) {
                    int corow = b_row_lane + np * 16;
                    ldm_x4(bf[np], sbW + SWZ(corow * 128 + ks * 32 + b_kb_lane));
                }
                #pragma unroll
                for (int mt = 0; mt < 2; mt++)
                    #pragma unroll
                    for (int np = 0; np < 2; np++) {
                        mma_s8(acc[mt][np * 2],     a[mt], bf[np][0], bf[np][1]);
                        mma_s8(acc[mt][np * 2 + 1], a[mt], bf[np][2], bf[np][3]);
                    }
            }
        }

        // buffer u fully consumed (fragments in regs) -> refill it NOW so the
        // cp.async overlaps the scattered-store epilogue below
        __syncthreads();
        if (k + 2 < ntiles) issue_load(k + 2, u);
        CP_COMMIT();

        // ------------------------- epilogue (float32 out) -------------------------
        {
            int mtile = mt0 + 74 * k;
            int b = mtile / 26, mtl = mtile - b * 26;
            int pbase = mtl * 128 + warp_m * 32 + (lane >> 2);
            const int2* s_ts = reinterpret_cast<const int2*>(smem + SMEM_TS);
            const int2* s_mm = reinterpret_cast<const int2*>(smem + SMEM_MM);
            float* outb = out + (size_t)((b << 8) + (half << 7)) * 3136;

            #pragma unroll
            for (int mt = 0; mt < 2; mt++) {
                int p0 = pbase + mt * 16;
                int p1 = p0 + 8;
                int oh0 = p0 / 58, ow0 = p0 - oh0 * 58;
                int oh1 = p1 / 58, ow1 = p1 - oh1 * 58;
                bool v0 = (ow0 < 56) && (oh0 < 56);
                bool v1 = (ow1 < 56) && (oh1 < 56);
                int pos0 = oh0 * 56 + ow0;
                int pos1 = oh1 * 56 + ow1;
                #pragma unroll
                for (int nt = 0; nt < 4; nt++) {
                    int co = warp_n * 32 + nt * 8 + (lane & 3) * 2;
                    int2 tsA = s_ts[co],     mmA = s_mm[co];
                    int2 tsB = s_ts[co + 1], mmB = s_mm[co + 1];
                    int* c = acc[mt][nt];
                    int x0 = (c[0] + tsA.x) >> tsA.y;
                    x0 = x0 < mmA.x ? mmA.x : (x0 > mmA.y ? mmA.y : x0);
                    int x1 = (c[1] + tsB.x) >> tsB.y;
                    x1 = x1 < mmB.x ? mmB.x : (x1 > mmB.y ? mmB.y : x1);
                    int x2 = (c[2] + tsA.x) >> tsA.y;
                    x2 = x2 < mmA.x ? mmA.x : (x2 > mmA.y ? mmA.y : x2);
                    int x3 = (c[3] + tsB.x) >> tsB.y;
                    x3 = x3 < mmB.x ? mmB.x : (x3 > mmB.y ? mmB.y : x3);
                    if (v0) {
                        outb[(size_t)co * 3136 + pos0]       = (float)x0;
                        outb[(size_t)(co + 1) * 3136 + pos0] = (float)x1;
                    }
                    if (v1) {
                        outb[(size_t)co * 3136 + pos1]       = (float)x2;
                        outb[(size_t)(co + 1) * 3136 + pos1] = (float)x3;
                    }
                }
            }
        }
    }
}

// ------------------------------- launch -------------------------------------
extern "C" void kernel_launch(void* const* d_in, const int* in_sizes, int n_in,
                              void* d_out, int out_size) {
    const int* x    = (const int*)d_in[0];
    const int* w    = (const int*)d_in[1];
    const int* t    = (const int*)d_in[2];
    const int* n    = (const int*)d_in[3];
    const int* amin = (const int*)d_in[4];
    const int* amax = (const int*)d_in[5];
    float* out = (float*)d_out;

    cudaFuncSetAttribute(conv_kernel, cudaFuncAttributeMaxDynamicSharedMemorySize, SMEM_TOTAL);

    pack_kernel<<<dim3(B_IMG, PW + 1), 256>>>(x, w);
    conv_kernel<<<GRID, NTHR, SMEM_TOTAL>>>(t, n, amin, amax, out);
}

// round 10
// speedup vs baseline: 1.0630x; 1.0630x over previous
#include <cuda_runtime.h>
#include <cstdint>

// ============================================================================
// ConvBnA int8: implicit-GEMM 3x3 conv via mma.sync m16n8k32 s8 (sm_100 safe)
//   out[b][co][oh][ow] = f32(clip(((conv + t[co]) >> (-n[co])), amin, amax))
// R10: CTA tile 192pix x 128co, warp tile 48x64 (7 ldmatrix per 24 mma),
// 8 warps; tap loop NOT unrolled (small body, low ptxas pressure).
// ============================================================================

#define B_IMG    32
#define CIN      128
#define HW       56
#define PW       58
#define IMG_ROWS 3456          // rows >= 3364 only feed discarded pixels
#define GRID     148
#define NTHR     256
#define ST_PIX   192           // supertile pixels
#define ST_PER_IMG 17          // 17*192=3264 >= 3246 covers all valid pixels
#define N_ST     (B_IMG * ST_PER_IMG)   // 544 per half

#define SWZ(o) ((o) ^ (((o) >> 3) & 0x70))

__device__ __align__(128) signed char g_xpad[(size_t)B_IMG * IMG_ROWS * CIN]; // 13.5 MB
__device__ __align__(128) signed char g_wpack[9 * 256 * CIN];                 // 288 KB

// ------------------------------- PTX helpers -------------------------------
__device__ __forceinline__ uint32_t smem_u32(const void* p) {
    uint32_t a;
    asm("{ .reg .u64 t; cvta.to.shared.u64 t, %1; cvt.u32.u64 %0, t; }"
        : "=r"(a) : "l"(p));
    return a;
}
#define CP16(sm, gp) \
    asm volatile("cp.async.cg.shared.global [%0], [%1], 16;" :: "r"(sm), "l"(gp) : "memory")
#define CP_COMMIT() asm volatile("cp.async.commit_group;" ::: "memory")
#define CP_WAIT1()  asm volatile("cp.async.wait_group 1;" ::: "memory")

__device__ __forceinline__ void ldm_x4(uint32_t* r, uint32_t addr) {
    asm volatile("ldmatrix.sync.aligned.m8n8.x4.shared.b16 {%0,%1,%2,%3}, [%4];"
                 : "=r"(r[0]), "=r"(r[1]), "=r"(r[2]), "=r"(r[3]) : "r"(addr));
}
__device__ __forceinline__ void mma_s8(int* c, const uint32_t* a, uint32_t b0, uint32_t b1) {
    asm volatile(
        "mma.sync.aligned.m16n8k32.row.col.s32.s8.s8.s32 "
        "{%0,%1,%2,%3}, {%4,%5,%6,%7}, {%8,%9}, {%0,%1,%2,%3};"
        : "+r"(c[0]), "+r"(c[1]), "+r"(c[2]), "+r"(c[3])
        : "r"(a[0]), "r"(a[1]), "r"(a[2]), "r"(a[3]), "r"(b0), "r"(b1));
}

// ------------------------------- merged pre-pass ----------------------------
// grid (32, 59), 256 threads.
//   blockIdx.y <  58 : pack x row h'=blockIdx.y of image b=blockIdx.x (pad fused)
//   blockIdx.y == 58 : pack 1/32 of the weights (fully coalesced reads)
__global__ void pack_kernel(const int* __restrict__ x, const int* __restrict__ w) {
    __shared__ unsigned char stage[128 * 57];
    int b = blockIdx.x, hp = blockIdx.y;
    int tid = threadIdx.x;     // 256

    if (hp == 58) {
        #pragma unroll
        for (int i = 0; i < 4; i++) {
            int pair = b * 1024 + i * 256 + tid;       // pair = co*128 + ci
            const int* src = w + (size_t)pair * 9;
            #pragma unroll
            for (int tap = 0; tap < 9; tap++)
                g_wpack[tap * 32768 + pair] = (signed char)src[tap];
        }
        return;
    }

    signed char* dst = g_xpad + ((size_t)b * IMG_ROWS + (size_t)hp * PW) * 128;
    if (hp == 0 || hp == 57) {
        for (int i = tid; i < 464; i += 256)
            reinterpret_cast<uint4*>(dst)[i] = make_uint4(0, 0, 0, 0);
        return;
    }
    if (tid < 16) {
        int seg = tid & 7, side = tid >> 3;
        reinterpret_cast<uint4*>(dst + (size_t)side * 57 * 128)[seg] = make_uint4(0, 0, 0, 0);
    }
    int h = hp - 1;
    const int* xb = x + (size_t)b * 128 * 3136 + h * 56;
    for (int flat = tid; flat < 128 * 64; flat += 256) {
        int c = flat >> 6, wv = flat & 63;
        if (wv < 56) stage[c * 57 + wv] = (unsigned char)xb[c * 3136 + wv];
    }
    __syncthreads();
    for (int f = tid; f < 56 * 32; f += 256) {
        int wv = f >> 5, c4 = f & 31;
        uint32_t v = (uint32_t)stage[(c4 * 4 + 0) * 57 + wv]
                   | ((uint32_t)stage[(c4 * 4 + 1) * 57 + wv] << 8)
                   | ((uint32_t)stage[(c4 * 4 + 2) * 57 + wv] << 16)
                   | ((uint32_t)stage[(c4 * 4 + 3) * 57 + wv] << 24);
        *reinterpret_cast<uint32_t*>(dst + (size_t)(1 + wv) * 128 + c4 * 4) = v;
    }
}

// ------------------------------- conv kernel --------------------------------
static constexpr int A_REGION_ROWS  = 310;                  // 192 + 118
static constexpr int A_REGION_BYTES = A_REGION_ROWS * 128;  // 39680 (128B-aligned)
static constexpr int SMEM_W   = 0;                          // 147456
static constexpr int SMEM_A   = 147456;                     // 2 * 39680 = 79360
static constexpr int SMEM_TS  = 226816;                     // int2[128]
static constexpr int SMEM_MM  = 227840;                     // int2[128]
static constexpr int SMEM_TOTAL = 228864;

__global__ void __launch_bounds__(NTHR, 1)
conv_kernel(const int* __restrict__ tvec, const int* __restrict__ nvec,
            const int* __restrict__ amin, const int* __restrict__ amax,
            float* __restrict__ out) {
    extern __shared__ __align__(1024) char smem[];
    const uint32_t sb = smem_u32(smem);
    const int tid = threadIdx.x;
    const int lane = tid & 31;
    const int wid = tid >> 5;          // 0..7
    const int warp_m = wid & 3;        // 4 warps over 192 pixels (48 each)
    const int warp_n = wid >> 2;       // 2 warps over 128 co (64 each)
    const int half = blockIdx.x & 1;
    const int s0 = blockIdx.x >> 1;    // first supertile (0..73)
    const int ntiles = (N_ST - 1 - s0) / 74 + 1;

    if (tid < 128) {
        int co = half * 128 + tid;
        *reinterpret_cast<int2*>(smem + SMEM_TS + tid * 8) = make_int2(tvec[co], -nvec[co]);
        *reinterpret_cast<int2*>(smem + SMEM_MM + tid * 8) = make_int2(amin[co], amax[co]);
    }

    auto issue_load = [&](int k, int u) {
        int stg = s0 + 74 * k;                         // global supertile
        int b = stg / ST_PER_IMG, st = stg - b * ST_PER_IMG;
        const signed char* src = g_xpad + ((size_t)b * IMG_ROWS + (size_t)st * ST_PIX) * 128;
        uint32_t abase = sb + SMEM_A + u * A_REGION_BYTES;
        #pragma unroll
        for (int i = 0; i < 10; i++) {
            int flat = i * NTHR + tid;                 // 2480 granules
            if (flat < A_REGION_BYTES / 16) {
                int off = flat << 4;
                CP16(abase + SWZ(off), src + off);
            }
        }
    };

    // resident weights + first A regions
    {
        #pragma unroll 6
        for (int i = 0; i < 36; i++) {
            int flat = i * NTHR + tid;                 // [0,9216)
            int tap = flat >> 10;
            int r = (flat >> 3) & 127, seg = flat & 7;
            const signed char* gp =
                g_wpack + ((size_t)(tap * 256 + half * 128 + r) << 7) + (seg << 4);
            CP16(sb + SMEM_W + (tap << 14) + SWZ((r << 7) | (seg << 4)), gp);
        }
        issue_load(0, 0);
        CP_COMMIT();
        if (ntiles > 1) issue_load(1, 1);
        CP_COMMIT();
    }

    for (int k = 0; k < ntiles; k++) {
        const int u = k & 1;
        const uint32_t sbA = sb + SMEM_A + u * A_REGION_BYTES;
        CP_WAIT1();
        __syncthreads();

        int acc[3][8][4];
        #pragma unroll
        for (int mt = 0; mt < 3; mt++)
            #pragma unroll
            for (int nt = 0; nt < 8; nt++)
                #pragma unroll
                for (int r = 0; r < 4; r++) acc[mt][nt][r] = 0;

        const int a_row_lane = warp_m * 48 + (lane & 15);
        const int a_kb_lane  = (lane >> 4) << 4;
        const int b_row_lane = warp_n * 64 + (lane & 7) + ((lane & 16) >> 1);
        const int b_kb_lane  = (lane & 8) << 1;

        #pragma unroll 1
        for (int tap = 0; tap < 9; tap++) {
            const int kh = (tap >= 6) ? 2 : (tap >= 3 ? 1 : 0);
            const int taprow = kh * PW + (tap - kh * 3);
            const uint32_t sbW = sb + SMEM_W + (tap << 14);
            #pragma unroll
            for (int ks = 0; ks < 4; ks++) {
                uint32_t a[3][4];
                #pragma unroll
                for (int mt = 0; mt < 3; mt++) {
                    int row = a_row_lane + mt * 16 + taprow;
                    ldm_x4(a[mt], sbA + SWZ(row * 128 + ks * 32 + a_kb_lane));
                }
                uint32_t bf[4][4];
                #pragma unroll
                for (int np = 0; np < 4; np++) {
                    int corow = b_row_lane + np * 16;
                    ldm_x4(bf[np], sbW + SWZ(corow * 128 + ks * 32 + b_kb_lane));
                }
                #pragma unroll
                for (int mt = 0; mt < 3; mt++)
                    #pragma unroll
                    for (int np = 0; np < 4; np++) {
                        mma_s8(acc[mt][np * 2],     a[mt], bf[np][0], bf[np][1]);
                        mma_s8(acc[mt][np * 2 + 1], a[mt], bf[np][2], bf[np][3]);
                    }
            }
        }

        // ------------------------- epilogue (float32 out) -------------------------
        {
            int stg = s0 + 74 * k;
            int b = stg / ST_PER_IMG, st = stg - b * ST_PER_IMG;
            int pbase = st * ST_PIX + warp_m * 48 + (lane >> 2);
            const int2* s_ts = reinterpret_cast<const int2*>(smem + SMEM_TS);
            const int2* s_mm = reinterpret_cast<const int2*>(smem + SMEM_MM);
            float* outb = out + (size_t)((b << 8) + (half << 7)) * 3136;

            #pragma unroll
            for (int mt = 0; mt < 3; mt++) {
                int p0 = pbase + mt * 16;
                int p1 = p0 + 8;
                int oh0 = p0 / 58, ow0 = p0 - oh0 * 58;
                int oh1 = p1 / 58, ow1 = p1 - oh1 * 58;
                bool v0 = (ow0 < 56) && (oh0 < 56);
                bool v1 = (ow1 < 56) && (oh1 < 56);
                int pos0 = oh0 * 56 + ow0;
                int pos1 = oh1 * 56 + ow1;
                #pragma unroll
                for (int nt = 0; nt < 8; nt++) {
                    int co = warp_n * 64 + nt * 8 + (lane & 3) * 2;
                    int2 tsA = s_ts[co],     mmA = s_mm[co];
                    int2 tsB = s_ts[co + 1], mmB = s_mm[co + 1];
                    int* c = acc[mt][nt];
                    int x0 = (c[0] + tsA.x) >> tsA.y;
                    x0 = x0 < mmA.x ? mmA.x : (x0 > mmA.y ? mmA.y : x0);
                    int x1 = (c[1] + tsB.x) >> tsB.y;
                    x1 = x1 < mmB.x ? mmB.x : (x1 > mmB.y ? mmB.y : x1);
                    int x2 = (c[2] + tsA.x) >> tsA.y;
                    x2 = x2 < mmA.x ? mmA.x : (x2 > mmA.y ? mmA.y : x2);
                    int x3 = (c[3] + tsB.x) >> tsB.y;
                    x3 = x3 < mmB.x ? mmB.x : (x3 > mmB.y ? mmB.y : x3);
                    if (v0) {
                        outb[(size_t)co * 3136 + pos0]       = (float)x0;
                        outb[(size_t)(co + 1) * 3136 + pos0] = (float)x1;
                    }
                    if (v1) {
                        outb[(size_t)co * 3136 + pos1]       = (float)x2;
                        outb[(size_t)(co + 1) * 3136 + pos1] = (float)x3;
                    }
                }
            }
        }

        __syncthreads();   // everyone done reading buffer u before refill
        if (k + 2 < ntiles) issue_load(k + 2, u);
        CP_COMMIT();
    }
}

// ------------------------------- launch -------------------------------------
extern "C" void kernel_launch(void* const* d_in, const int* in_sizes, int n_in,
                              void* d_out, int out_size) {
    const int* x    = (const int*)d_in[0];
    const int* w    = (const int*)d_in[1];
    const int* t    = (const int*)d_in[2];
    const int* n    = (const int*)d_in[3];
    const int* amin = (const int*)d_in[4];
    const int* amax = (const int*)d_in[5];
    float* out = (float*)d_out;

    cudaFuncSetAttribute(conv_kernel, cudaFuncAttributeMaxDynamicSharedMemorySize, SMEM_TOTAL);

    pack_kernel<<<dim3(B_IMG, PW + 1), 256>>>(x, w);
    conv_kernel<<<GRID, NTHR, SMEM_TOTAL>>>(t, n, amin, amax, out);
}

// round 12
// speedup vs baseline: 1.1361x; 1.0688x over previous
#include <cuda_runtime.h>
#include <cstdint>

// ============================================================================
// ConvBnA int8: implicit-GEMM 3x3 conv via mma.sync m16n8k32 s8 (sm_100 safe)
//   out[b][co][oh][ow] = f32(clip(((conv + t[co]) >> (-n[co])), amin, amax))
// R12 (= R11 resubmit): conv identical to R10 (proven 100.7us, legacy-IMMA
// floor). pack_x rewritten: uint4 loads + transpose-on-smem-write, phase 2 is
// a pure vectorized copy.
// ============================================================================

#define B_IMG    32
#define CIN      128
#define HW       56
#define PW       58
#define IMG_ROWS 3456          // rows >= 3364 only feed discarded pixels
#define GRID     148
#define NTHR     256
#define ST_PIX   192           // supertile pixels
#define ST_PER_IMG 17          // 17*192=3264 >= 3246 covers all valid pixels
#define N_ST     (B_IMG * ST_PER_IMG)   // 544 per half

#define SWZ(o) ((o) ^ (((o) >> 3) & 0x70))

__device__ __align__(128) signed char g_xpad[(size_t)B_IMG * IMG_ROWS * CIN]; // 13.5 MB
__device__ __align__(128) signed char g_wpack[9 * 256 * CIN];                 // 288 KB

// ------------------------------- PTX helpers -------------------------------
__device__ __forceinline__ uint32_t smem_u32(const void* p) {
    uint32_t a;
    asm("{ .reg .u64 t; cvta.to.shared.u64 t, %1; cvt.u32.u64 %0, t; }"
        : "=r"(a) : "l"(p));
    return a;
}
#define CP16(sm, gp) \
    asm volatile("cp.async.cg.shared.global [%0], [%1], 16;" :: "r"(sm), "l"(gp) : "memory")
#define CP_COMMIT() asm volatile("cp.async.commit_group;" ::: "memory")
#define CP_WAIT1()  asm volatile("cp.async.wait_group 1;" ::: "memory")

__device__ __forceinline__ void ldm_x4(uint32_t* r, uint32_t addr) {
    asm volatile("ldmatrix.sync.aligned.m8n8.x4.shared.b16 {%0,%1,%2,%3}, [%4];"
                 : "=r"(r[0]), "=r"(r[1]), "=r"(r[2]), "=r"(r[3]) : "r"(addr));
}
__device__ __forceinline__ void mma_s8(int* c, const uint32_t* a, uint32_t b0, uint32_t b1) {
    asm volatile(
        "mma.sync.aligned.m16n8k32.row.col.s32.s8.s8.s32 "
        "{%0,%1,%2,%3}, {%4,%5,%6,%7}, {%8,%9}, {%0,%1,%2,%3};"
        : "+r"(c[0]), "+r"(c[1]), "+r"(c[2]), "+r"(c[3])
        : "r"(a[0]), "r"(a[1]), "r"(a[2]), "r"(a[3]), "r"(b0), "r"(b1));
}

// ------------------------------- merged pre-pass ----------------------------
// grid (32, 59), 256 threads.
//   blockIdx.y <  58 : pack x row h'=blockIdx.y of image b=blockIdx.x (pad fused)
//   blockIdx.y == 58 : pack 1/32 of the weights
__global__ void pack_kernel(const int* __restrict__ x, const int* __restrict__ w) {
    __shared__ unsigned char stage2[56 * 128];   // [w][c], transposed tile
    int b = blockIdx.x, hp = blockIdx.y;
    int tid = threadIdx.x;     // 256

    if (hp == 58) {
        #pragma unroll
        for (int i = 0; i < 4; i++) {
            int pair = b * 1024 + i * 256 + tid;       // pair = co*128 + ci
            const int* src = w + (size_t)pair * 9;
            #pragma unroll
            for (int tap = 0; tap < 9; tap++)
                g_wpack[tap * 32768 + pair] = (signed char)src[tap];
        }
        return;
    }

    signed char* dst = g_xpad + ((size_t)b * IMG_ROWS + (size_t)hp * PW) * 128;
    if (hp == 0 || hp == 57) {                 // full zero row: 58*128 B
        for (int i = tid; i < 464; i += 256)
            reinterpret_cast<uint4*>(dst)[i] = make_uint4(0, 0, 0, 0);
        return;
    }
    // zero w'=0 and w'=57 columns
    if (tid < 16) {
        int seg = tid & 7, side = tid >> 3;
        reinterpret_cast<uint4*>(dst + (size_t)side * 57 * 128)[seg] = make_uint4(0, 0, 0, 0);
    }

    // phase 1: vectorized NCHW reads, transpose on smem write
    {
        int h = hp - 1;
        int c = tid >> 1;                      // 0..127
        int w0 = (tid & 1) * 28;               // 0 or 28
        const uint4* src = reinterpret_cast<const uint4*>(
            x + (size_t)b * 128 * 3136 + (size_t)c * 3136 + h * 56 + w0);
        #pragma unroll
        for (int i = 0; i < 7; i++) {
            uint4 v = src[i];
            int wv = w0 + i * 4;
            stage2[(wv + 0) * 128 + c] = (unsigned char)(int)v.x;
            stage2[(wv + 1) * 128 + c] = (unsigned char)(int)v.y;
            stage2[(wv + 2) * 128 + c] = (unsigned char)(int)v.z;
            stage2[(wv + 3) * 128 + c] = (unsigned char)(int)v.w;
        }
    }
    __syncthreads();

    // phase 2: pure vectorized copy, stage2[w][c] -> dst row w'=1+w
    {
        const uint4* s4 = reinterpret_cast<const uint4*>(stage2);
        uint4* d4 = reinterpret_cast<uint4*>(dst + 128);   // w'=1
        #pragma unroll
        for (int i = 0; i < 2; i++) {
            int f = i * 256 + tid;                         // 448 uint4 total
            if (f < 448) d4[f] = s4[f];
        }
    }
}

// ------------------------------- conv kernel --------------------------------
static constexpr int A_REGION_ROWS  = 310;                  // 192 + 118
static constexpr int A_REGION_BYTES = A_REGION_ROWS * 128;  // 39680 (128B-aligned)
static constexpr int SMEM_W   = 0;                          // 147456
static constexpr int SMEM_A   = 147456;                     // 2 * 39680 = 79360
static constexpr int SMEM_TS  = 226816;                     // int2[128]
static constexpr int SMEM_MM  = 227840;                     // int2[128]
static constexpr int SMEM_TOTAL = 228864;

__global__ void __launch_bounds__(NTHR, 1)
conv_kernel(const int* __restrict__ tvec, const int* __restrict__ nvec,
            const int* __restrict__ amin, const int* __restrict__ amax,
            float* __restrict__ out) {
    extern __shared__ __align__(1024) char smem[];
    const uint32_t sb = smem_u32(smem);
    const int tid = threadIdx.x;
    const int lane = tid & 31;
    const int wid = tid >> 5;          // 0..7
    const int warp_m = wid & 3;        // 4 warps over 192 pixels (48 each)
    const int warp_n = wid >> 2;       // 2 warps over 128 co (64 each)
    const int half = blockIdx.x & 1;
    const int s0 = blockIdx.x >> 1;    // first supertile (0..73)
    const int ntiles = (N_ST - 1 - s0) / 74 + 1;

    if (tid < 128) {
        int co = half * 128 + tid;
        *reinterpret_cast<int2*>(smem + SMEM_TS + tid * 8) = make_int2(tvec[co], -nvec[co]);
        *reinterpret_cast<int2*>(smem + SMEM_MM + tid * 8) = make_int2(amin[co], amax[co]);
    }

    auto issue_load = [&](int k, int u) {
        int stg = s0 + 74 * k;                         // global supertile
        int b = stg / ST_PER_IMG, st = stg - b * ST_PER_IMG;
        const signed char* src = g_xpad + ((size_t)b * IMG_ROWS + (size_t)st * ST_PIX) * 128;
        uint32_t abase = sb + SMEM_A + u * A_REGION_BYTES;
        #pragma unroll
        for (int i = 0; i < 10; i++) {
            int flat = i * NTHR + tid;                 // 2480 granules
            if (flat < A_REGION_BYTES / 16) {
                int off = flat << 4;
                CP16(abase + SWZ(off), src + off);
            }
        }
    };

    // resident weights + first A regions
    {
        #pragma unroll 6
        for (int i = 0; i < 36; i++) {
            int flat = i * NTHR + tid;                 // [0,9216)
            int tap = flat >> 10;
            int r = (flat >> 3) & 127, seg = flat & 7;
            const signed char* gp =
                g_wpack + ((size_t)(tap * 256 + half * 128 + r) << 7) + (seg << 4);
            CP16(sb + SMEM_W + (tap << 14) + SWZ((r << 7) | (seg << 4)), gp);
        }
        issue_load(0, 0);
        CP_COMMIT();
        if (ntiles > 1) issue_load(1, 1);
        CP_COMMIT();
    }

    for (int k = 0; k < ntiles; k++) {
        const int u = k & 1;
        const uint32_t sbA = sb + SMEM_A + u * A_REGION_BYTES;
        CP_WAIT1();
        __syncthreads();

        int acc[3][8][4];
        #pragma unroll
        for (int mt = 0; mt < 3; mt++)
            #pragma unroll
            for (int nt = 0; nt < 8; nt++)
                #pragma unroll
                for (int r = 0; r < 4; r++) acc[mt][nt][r] = 0;

        const int a_row_lane = warp_m * 48 + (lane & 15);
        const int a_kb_lane  = (lane >> 4) << 4;
        const int b_row_lane = warp_n * 64 + (lane & 7) + ((lane & 16) >> 1);
        const int b_kb_lane  = (lane & 8) << 1;

        #pragma unroll 1
        for (int tap = 0; tap < 9; tap++) {
            const int kh = (tap >= 6) ? 2 : (tap >= 3 ? 1 : 0);
            const int taprow = kh * PW + (tap - kh * 3);
            const uint32_t sbW = sb + SMEM_W + (tap << 14);
            #pragma unroll
            for (int ks = 0; ks < 4; ks++) {
                uint32_t a[3][4];
                #pragma unroll
                for (int mt = 0; mt < 3; mt++) {
                    int row = a_row_lane + mt * 16 + taprow;
                    ldm_x4(a[mt], sbA + SWZ(row * 128 + ks * 32 + a_kb_lane));
                }
                uint32_t bf[4][4];
                #pragma unroll
                for (int np = 0; np < 4; np++) {
                    int corow = b_row_lane + np * 16;
                    ldm_x4(bf[np], sbW + SWZ(corow * 128 + ks * 32 + b_kb_lane));
                }
                #pragma unroll
                for (int mt = 0; mt < 3; mt++)
                    #pragma unroll
                    for (int np = 0; np < 4; np++) {
                        mma_s8(acc[mt][np * 2],     a[mt], bf[np][0], bf[np][1]);
                        mma_s8(acc[mt][np * 2 + 1], a[mt], bf[np][2], bf[np][3]);
                    }
            }
        }

        // ------------------------- epilogue (float32 out) -------------------------
        {
            int stg = s0 + 74 * k;
            int b = stg / ST_PER_IMG, st = stg - b * ST_PER_IMG;
            int pbase = st * ST_PIX + warp_m * 48 + (lane >> 2);
            const int2* s_ts = reinterpret_cast<const int2*>(smem + SMEM_TS);
            const int2* s_mm = reinterpret_cast<const int2*>(smem + SMEM_MM);
            float* outb = out + (size_t)((b << 8) + (half << 7)) * 3136;

            #pragma unroll
            for (int mt = 0; mt < 3; mt++) {
                int p0 = pbase + mt * 16;
                int p1 = p0 + 8;
                int oh0 = p0 / 58, ow0 = p0 - oh0 * 58;
                int oh1 = p1 / 58, ow1 = p1 - oh1 * 58;
                bool v0 = (ow0 < 56) && (oh0 < 56);
                bool v1 = (ow1 < 56) && (oh1 < 56);
                int pos0 = oh0 * 56 + ow0;
                int pos1 = oh1 * 56 + ow1;
                #pragma unroll
                for (int nt = 0; nt < 8; nt++) {
                    int co = warp_n * 64 + nt * 8 + (lane & 3) * 2;
                    int2 tsA = s_ts[co],     mmA = s_mm[co];
                    int2 tsB = s_ts[co + 1], mmB = s_mm[co + 1];
                    int* c = acc[mt][nt];
                    int x0 = (c[0] + tsA.x) >> tsA.y;
                    x0 = x0 < mmA.x ? mmA.x : (x0 > mmA.y ? mmA.y : x0);
                    int x1 = (c[1] + tsB.x) >> tsB.y;
                    x1 = x1 < mmB.x ? mmB.x : (x1 > mmB.y ? mmB.y : x1);
                    int x2 = (c[2] + tsA.x) >> tsA.y;
                    x2 = x2 < mmA.x ? mmA.x : (x2 > mmA.y ? mmA.y : x2);
                    int x3 = (c[3] + tsB.x) >> tsB.y;
                    x3 = x3 < mmB.x ? mmB.x : (x3 > mmB.y ? mmB.y : x3);
                    if (v0) {
                        outb[(size_t)co * 3136 + pos0]       = (float)x0;
                        outb[(size_t)(co + 1) * 3136 + pos0] = (float)x1;
                    }
                    if (v1) {
                        outb[(size_t)co * 3136 + pos1]       = (float)x2;
                        outb[(size_t)(co + 1) * 3136 + pos1] = (float)x3;
                    }
                }
            }
        }

        __syncthreads();   // everyone done reading buffer u before refill
        if (k + 2 < ntiles) issue_load(k + 2, u);
        CP_COMMIT();
    }
}

// ------------------------------- launch -------------------------------------
extern "C" void kernel_launch(void* const* d_in, const int* in_sizes, int n_in,
                              void* d_out, int out_size) {
    const int* x    = (const int*)d_in[0];
    const int* w    = (const int*)d_in[1];
    const int* t    = (const int*)d_in[2];
    const int* n    = (const int*)d_in[3];
    const int* amin = (const int*)d_in[4];
    const int* amax = (const int*)d_in[5];
    float* out = (float*)d_out;

    cudaFuncSetAttribute(conv_kernel, cudaFuncAttributeMaxDynamicSharedMemorySize, SMEM_TOTAL);

    pack_kernel<<<dim3(B_IMG, PW + 1), 256>>>(x, w);
    conv_kernel<<<GRID, NTHR, SMEM_TOTAL>>>(t, n, amin, amax, out);
}